// round 6
// baseline (speedup 1.0000x reference)
#include <cuda_runtime.h>
#include <cuda_fp16.h>
#include <cstdint>

#define NB_CAT  8192
#define RANK    16
#define N_COLS  4

// R6: fp16 table (R5 win) + MLP restructure.
//  - Index int4 loads software-pipelined one iteration ahead (hides ~600cyc
//    DRAM latency that serialized each iteration in R5).
//  - All 8 table row-gathers issued back-to-back into register arrays before
//    any conversion/FMA (guaranteed MLP=8 per warp in SASS).
//  - __launch_bounds__(256,6): 42-reg budget, 48 warps/SM. In-flight rows
//    ~= 48*8 = 384/SM > ~210 needed to saturate the 1 wf/cyc L1tex ceiling.

__device__ __half2 g_cfh[N_COLS * NB_CAT * RANK / 2];   // 4 MB, layout = cf

__global__ __launch_bounds__(256) void convert_cf_kernel(const float* __restrict__ cf)
{
    const int i = blockIdx.x * blockDim.x + threadIdx.x;   // half2 index
    const int n = N_COLS * NB_CAT * RANK / 2;              // 1,048,576
    if (i < n) {
        const float2 v = ((const float2*)cf)[i];
        g_cfh[i] = __float22half2_rn(v);
    }
}

__global__ __launch_bounds__(256, 6) void pair_cov_kernel(
    const int*   __restrict__ x,
    const int*   __restrict__ y,
    const float* __restrict__ stdv,   // [N_COLS, NB_CAT]
    float*       __restrict__ out,
    int n_pairs)
{
    const int lane = threadIdx.x & 31;
    const int sub  = lane & 3;        // 8B chunk within the 32B fp16 row
    const int unit = lane >> 2;       // pair slot within warp-iter (0..7)

    const int warp_global = (int)((blockIdx.x * blockDim.x + threadIdx.x) >> 5);
    const int nwarps      = (int)((gridDim.x * blockDim.x) >> 5);

    // row r = 4 uint2 (32B); lane `sub` owns chunk cfh[r*4 + sub]
    const uint2* cfh = (const uint2*)g_cfh;

    int base = warp_global * 8;
    if (base >= n_pairs) return;

    // Prime the index pipeline
    int4 xi = __ldcg((const int4*)x + base + unit);
    int4 yi = __ldcg((const int4*)y + base + unit);

    while (base < n_pairs) {
        const int nbase = base + nwarps * 8;

        // ---- Phase 1: issue all 8 row gathers back-to-back (MLP=8) ----
        uint2 av[N_COLS], bv[N_COLS];
        #pragma unroll
        for (int c = 0; c < N_COLS; c++) {
            const int xc = (c == 0) ? xi.x : (c == 1) ? xi.y : (c == 2) ? xi.z : xi.w;
            const int yc = (c == 0) ? yi.x : (c == 1) ? yi.y : (c == 2) ? yi.z : yi.w;
            av[c] = cfh[(size_t)(c * NB_CAT + xc) * 4 + sub];
            bv[c] = cfh[(size_t)(c * NB_CAT + yc) * 4 + sub];
        }

        // ---- Phase 2: prefetch next iteration's indices (hide DRAM lat) ----
        int4 nxi, nyi;
        if (nbase < n_pairs) {
            nxi = __ldcg((const int4*)x + nbase + unit);
            nyi = __ldcg((const int4*)y + nbase + unit);
        }

        // ---- Phase 3: convert + accumulate ----
        float acc = 0.0f;
        #pragma unroll
        for (int c = 0; c < N_COLS; c++) {
            const float2 a0 = __half22float2(*(const __half2*)&av[c].x);
            const float2 a1 = __half22float2(*(const __half2*)&av[c].y);
            const float2 b0 = __half22float2(*(const __half2*)&bv[c].x);
            const float2 b1 = __half22float2(*(const __half2*)&bv[c].y);
            acc += a0.x * b0.x;
            acc += a0.y * b0.y;
            acc += a1.x * b1.x;
            acc += a1.y * b1.y;
        }

        // Diagonal term (fp32 std, exact): lane `sub` owns column `sub`
        {
            const int xd = (sub == 0) ? xi.x : (sub == 1) ? xi.y : (sub == 2) ? xi.z : xi.w;
            const int yd = (sub == 0) ? yi.x : (sub == 1) ? yi.y : (sub == 2) ? yi.z : yi.w;
            if (xd == yd) {
                const float s = stdv[sub * NB_CAT + xd];
                acc += s * s;
            }
        }

        // Reduce over the 4 chunk lanes; lane 0 of each unit writes
        acc += __shfl_xor_sync(0xffffffffu, acc, 1);
        acc += __shfl_xor_sync(0xffffffffu, acc, 2);

        if (sub == 0) {
            out[base + unit] = acc;
        }

        xi = nxi;
        yi = nyi;
        base = nbase;
    }
}

extern "C" void kernel_launch(void* const* d_in, const int* in_sizes, int n_in,
                              void* d_out, int out_size)
{
    const int*   x    = (const int*)d_in[0];
    const int*   y    = (const int*)d_in[1];
    const float* cf   = (const float*)d_in[2];
    const float* stdv = (const float*)d_in[3];
    float*       out  = (float*)d_out;

    const int n_pairs = out_size;  // 1048576

    // 1) Convert covar_factor fp32 -> fp16
    {
        const int n = N_COLS * NB_CAT * RANK / 2;
        convert_cf_kernel<<<(n + 255) / 256, 256>>>(cf);
    }

    // 2) Main gather kernel: single resident wave at 6 blocks/SM
    {
        const int threads = 256;
        const int blocks  = 148 * 6;
        pair_cov_kernel<<<blocks, threads>>>(x, y, stdv, out, n_pairs);
    }
}